// round 5
// baseline (speedup 1.0000x reference)
#include <cuda_runtime.h>
#include <cuda_fp16.h>
#include <cstdint>

// ---------------- static scratch ----------------
#define TBITS 21
#define TSIZE (1u << TBITS)
#define TMASK (TSIZE - 1u)
#define EMPTYK 0xFFFFFFFFu
#define MAXE 1050624
#define MAXN 40960
#define DUPCAP 262144

__device__ unsigned int  g_hkey[TSIZE];
__device__ unsigned char g_dupflag[TSIZE];
__device__ int           g_dupid[TSIZE];
__device__ int           g_soe[MAXE];   // pass1: slot of edge; pass2 (k_dupacc): rev-offset code
__device__ __align__(16) float g_agg[MAXN * 64];
__device__ __align__(16) float g_dupsum[(size_t)DUPCAP * 64];
__device__ int           g_ndup;

// ---------------- helpers ----------------
__device__ __forceinline__ unsigned int mixh(unsigned int x) {
    x ^= x >> 16; x *= 0x7feb352du;
    x ^= x >> 15; x *= 0x846ca68bu;
    x ^= x >> 16; return x;
}

__device__ __forceinline__ void red4(float* p, float4 v) {
    asm volatile("red.global.add.v4.f32 [%0], {%1,%2,%3,%4};"
                 :: "l"(p), "f"(v.x), "f"(v.y), "f"(v.z), "f"(v.w) : "memory");
}

// fp16 split: x -> hi(f16x2) + lo(f16x2 of residual); elem .x in low half
__device__ __forceinline__ void cvt_split(float2 x, uint32_t& hi, uint32_t& lo) {
    __half2 h = __float22half2_rn(x);
    float2 hb = __half22float2(h);
    __half2 l = __floats2half2_rn(x.x - hb.x, x.y - hb.y);
    hi = *(uint32_t*)&h;
    lo = *(uint32_t*)&l;
}

__device__ __forceinline__ void mma16816(float* c, const uint32_t* a,
                                         uint32_t b0, uint32_t b1) {
    asm("mma.sync.aligned.m16n8k16.row.col.f32.f16.f16.f32 "
        "{%0,%1,%2,%3}, {%4,%5,%6,%7}, {%8,%9}, {%0,%1,%2,%3};"
        : "+f"(c[0]), "+f"(c[1]), "+f"(c[2]), "+f"(c[3])
        : "r"(a[0]), "r"(a[1]), "r"(a[2]), "r"(a[3]), "r"(b0), "r"(b1));
}

// ---------------- kernel: hash insert + node aggregation ----------------
__global__ __launch_bounds__(256) void k_insert(const float* __restrict__ ef,
                                                const int* __restrict__ esrc,
                                                const int* __restrict__ edst,
                                                int nn, int E) {
    int i = blockIdx.x * 256 + threadIdx.x;
    if (i >= E) return;
    int s = esrc[i], d = edst[i];
    unsigned int key = (unsigned int)s * (unsigned int)nn + (unsigned int)d;
    unsigned int h = mixh(key) & TMASK;
    for (;;) {
        unsigned int prev = atomicCAS(&g_hkey[h], EMPTYK, key);
        if (prev == EMPTYK) break;
        if (prev == key) { g_dupflag[h] = 1; break; }
        h = (h + 1u) & TMASK;
    }
    g_soe[i] = (int)h;

    const float4* row = (const float4*)(ef + (size_t)i * 64);
    float* ar = g_agg + (size_t)d * 64;
#pragma unroll
    for (int c = 0; c < 16; c++) red4(ar + 4 * c, row[c]);
}

// ---------------- kernel: assign dup ids ----------------
__global__ void k_dupassign() {
    int t = blockIdx.x * 256 + threadIdx.x;
    if (t >= (int)TSIZE) return;
    if (g_dupflag[t]) {
        int d = atomicAdd(&g_ndup, 1);
        if (d < DUPCAP) {
            g_dupid[t] = d;
            float4* p = (float4*)(g_dupsum + (size_t)d * 64);
#pragma unroll
            for (int c = 0; c < 16; c++) p[c] = make_float4(0.f, 0.f, 0.f, 0.f);
        } else g_dupid[t] = -1;
    } else {
        g_dupid[t] = -1;
    }
}

// ---------------- kernel: accumulate dup groups + encode rev-offset ----------------
__global__ __launch_bounds__(256) void k_dupacc(const float* __restrict__ ef, int E) {
    int i = blockIdx.x * 256 + threadIdx.x;
    if (i >= E) return;
    int d = g_dupid[g_soe[i]];
    g_soe[i] = (d >= 0) ? d * 256 : -1;     // rev-offset code (bytes into g_dupsum)
    if (d < 0) return;
    const float4* row = (const float4*)(ef + (size_t)i * 64);
    float* p = g_dupsum + (size_t)d * 64;
#pragma unroll
    for (int c = 0; c < 16; c++) red4(p + 4 * c, row[c]);
}

// ---------------- fused: mirror-paired tiles, float4 K-permuted HMMA ----------------
// K-permute: mma k-slots {2q,2q+1,2q+8,2q+9} of block kb <- data cols kb*16+4q+{0..3}
// N-permute: (nb, n) -> out col 16*(nb>>1) + 4*(n>>1) + 2*(nb&1) + (n&1)
// Rev data for row j (non-dup) = xf[j^2] (partner's ef float4, in-register).
__global__ __launch_bounds__(256, 2) void k_fused_mma(const float* __restrict__ ef,
                                                      const int* __restrict__ esrc,
                                                      const float* __restrict__ W,
                                                      const float* __restrict__ bias,
                                                      float* __restrict__ out, int E) {
    __shared__ uint4 Bf[8][8][32];     // [kb][nb][lane] = (bh0,bh1,bl0,bl1)  32KB
    __shared__ float bias_sh[64];

    const int tid  = threadIdx.x;
    const int lane = tid & 31;
    const int wid  = tid >> 5;
    const int q    = lane & 3;
    const int g    = lane >> 2;

    // Build W fragments with K- and N-permutation applied.
    for (int idx = tid; idx < 2048; idx += 256) {
        int kb = idx >> 8, nb = (idx >> 5) & 7, L = idx & 31;
        int qq = L & 3, nB = L >> 2;
        int n = 16 * (nb >> 1) + ((nB >> 1) << 2) + ((nb & 1) << 1) + (nB & 1);
        int d0 = kb * 16 + 4 * qq;
        uint32_t h0, l0, h1, l1;
        cvt_split(make_float2(W[d0 * 64 + n], W[(d0 + 1) * 64 + n]), h0, l0);
        cvt_split(make_float2(W[(d0 + 2) * 64 + n], W[(d0 + 3) * 64 + n]), h1, l1);
        Bf[kb][nb][L] = make_uint4(h0, h1, l0, l1);
    }
    if (tid < 64) bias_sh[tid] = bias[tid];
    __syncthreads();

    const int E2 = E >> 1;
    const int ntiles = (E2 + 15) >> 4;

    for (int t = blockIdx.x * 8 + wid; t < ntiles; t += gridDim.x * 8) {
        const int base = t * 16;
        int e[4]; bool val[2];
        uint32_t oef[4], oagg[4], orev[4];
#pragma unroll
        for (int j2 = 0; j2 < 2; j2++) {
            int f = base + 8 * j2 + g;
            bool v = f < E2;
            int fc = v ? f : 0;
            e[j2] = fc; e[2 + j2] = fc + E2;
            val[j2] = v;
        }
#pragma unroll
        for (int j = 0; j < 4; j++) {
            oef[j]  = (uint32_t)e[j] * 256u;
            oagg[j] = (uint32_t)__ldg(&esrc[e[j]]) * 256u;
            orev[j] = (uint32_t)__ldg(&g_soe[e[j ^ 2]]);   // -1 or dupsum byte offset
        }

        float acc[2][8][4];
#pragma unroll
        for (int mb = 0; mb < 2; mb++)
#pragma unroll
            for (int nb = 0; nb < 8; nb++)
#pragma unroll
                for (int c = 0; c < 4; c++) acc[mb][nb][c] = 0.f;

#pragma unroll 1
        for (int kb = 0; kb < 4; kb++) {
            const uint32_t foff = (uint32_t)(kb * 4 + q) * 16u;
            // raw ef float4 for all 4 rows (also partner rev data)
            float4 xf[4];
#pragma unroll
            for (int j = 0; j < 4; j++)
                xf[j] = *(const float4*)((const char*)ef + (oef[j] + foff));

            // ---- phase A: W block kb (h = ef) ----
#pragma unroll
            for (int mb = 0; mb < 2; mb++) {
                uint32_t ah[4], al[4];
                cvt_split(make_float2(xf[2 * mb + 0].x, xf[2 * mb + 0].y), ah[0], al[0]);
                cvt_split(make_float2(xf[2 * mb + 1].x, xf[2 * mb + 1].y), ah[1], al[1]);
                cvt_split(make_float2(xf[2 * mb + 0].z, xf[2 * mb + 0].w), ah[2], al[2]);
                cvt_split(make_float2(xf[2 * mb + 1].z, xf[2 * mb + 1].w), ah[3], al[3]);
#pragma unroll
                for (int nb = 0; nb < 8; nb++) {
                    uint4 b = Bf[kb][nb][lane];
                    mma16816(acc[mb][nb], ah, b.x, b.y);
                    mma16816(acc[mb][nb], al, b.x, b.y);
                    mma16816(acc[mb][nb], ah, b.z, b.w);
                }
            }
            // ---- phase B: W block kb+4 (h = agg[src] - rev) ----
#pragma unroll
            for (int mb = 0; mb < 2; mb++) {
                uint32_t ah[4], al[4];
#pragma unroll
                for (int j2 = 0; j2 < 2; j2++) {
                    int j = 2 * mb + j2;
                    float4 a = *(const float4*)((const char*)g_agg + (oagg[j] + foff));
                    float4 r;
                    if (orev[j] != 0xFFFFFFFFu)
                        r = *(const float4*)((const char*)g_dupsum + (orev[j] + foff));
                    else
                        r = xf[j ^ 2];
                    cvt_split(make_float2(a.x - r.x, a.y - r.y), ah[j2], al[j2]);
                    cvt_split(make_float2(a.z - r.z, a.w - r.w), ah[2 + j2], al[2 + j2]);
                }
#pragma unroll
                for (int nb = 0; nb < 8; nb++) {
                    uint4 b = Bf[kb + 4][nb][lane];
                    mma16816(acc[mb][nb], ah, b.x, b.y);
                    mma16816(acc[mb][nb], al, b.x, b.y);
                    mma16816(acc[mb][nb], ah, b.z, b.w);
                }
            }
        }

        // ---- epilogue: bias + relu + float4 stores (N-permuted) ----
#pragma unroll
        for (int mb = 0; mb < 2; mb++) {
#pragma unroll
            for (int tt = 0; tt < 4; tt++) {
                int col = 16 * tt + 4 * q;
                float4 b4 = *(const float4*)(bias_sh + col);
                if (val[0] || mb == 0) {}   // keep structure simple; guarded below
                if ((mb == 0 ? val[0] : val[0])) {
                    float4 o;
                    o.x = fmaxf(acc[mb][2 * tt][0] + b4.x, 0.f);
                    o.y = fmaxf(acc[mb][2 * tt][1] + b4.y, 0.f);
                    o.z = fmaxf(acc[mb][2 * tt + 1][0] + b4.z, 0.f);
                    o.w = fmaxf(acc[mb][2 * tt + 1][1] + b4.w, 0.f);
                    *(float4*)(out + (size_t)e[2 * mb] * 64 + col) = o;
                }
                if (val[1]) {
                    float4 o;
                    o.x = fmaxf(acc[mb][2 * tt][2] + b4.x, 0.f);
                    o.y = fmaxf(acc[mb][2 * tt][3] + b4.y, 0.f);
                    o.z = fmaxf(acc[mb][2 * tt + 1][2] + b4.z, 0.f);
                    o.w = fmaxf(acc[mb][2 * tt + 1][3] + b4.w, 0.f);
                    *(float4*)(out + (size_t)e[2 * mb + 1] * 64 + col) = o;
                }
            }
        }
    }
}

// ---------------- launch ----------------
extern "C" void kernel_launch(void* const* d_in, const int* in_sizes, int n_in,
                              void* d_out, int out_size) {
    const float* ef   = (const float*)d_in[0];
    const int*   esrc = (const int*)d_in[1];
    const int*   edst = (const int*)d_in[2];
    const float* W    = (const float*)d_in[5];
    const float* bias = (const float*)d_in[6];
    float* out = (float*)d_out;

    int E  = in_sizes[1];
    int nn = in_sizes[3];

    void *p_hkey, *p_flag, *p_agg, *p_ndup;
    cudaGetSymbolAddress(&p_hkey, g_hkey);
    cudaGetSymbolAddress(&p_flag, g_dupflag);
    cudaGetSymbolAddress(&p_agg,  g_agg);
    cudaGetSymbolAddress(&p_ndup, g_ndup);

    cudaMemsetAsync(p_hkey, 0xFF, (size_t)TSIZE * 4);
    cudaMemsetAsync(p_flag, 0x00, (size_t)TSIZE);
    cudaMemsetAsync(p_agg,  0x00, (size_t)nn * 64 * 4);
    cudaMemsetAsync(p_ndup, 0x00, 4);

    k_insert<<<(E + 255) / 256, 256>>>(ef, esrc, edst, nn, E);
    k_dupassign<<<((int)TSIZE + 255) / 256, 256>>>();
    k_dupacc<<<(E + 255) / 256, 256>>>(ef, E);

    k_fused_mma<<<296, 256>>>(ef, esrc, W, bias, out, E);
}

// round 6
// speedup vs baseline: 1.0238x; 1.0238x over previous
#include <cuda_runtime.h>
#include <cuda_fp16.h>
#include <cstdint>

// ---------------- static scratch ----------------
#define TBITS 21
#define TSIZE (1u << TBITS)
#define TMASK (TSIZE - 1u)
#define EMPTYK 0xFFFFFFFFu
#define MAXE 1050624
#define MAXN 40960
#define DUPCAP 131072

__device__ unsigned int  g_hkey[TSIZE];
__device__ unsigned char g_dupflag[TSIZE];
__device__ int           g_dupid[TSIZE];
__device__ int           g_soe[MAXE];   // pass1: slot of edge; pass2: rev-offset code
__device__ __align__(16) float g_agg[MAXN * 64];
__device__ __align__(16) float g_dupsum[(size_t)DUPCAP * 64];
__device__ int           g_ndup;

// ---------------- helpers ----------------
__device__ __forceinline__ unsigned int mixh(unsigned int x) {
    x ^= x >> 16; x *= 0x7feb352du;
    x ^= x >> 15; x *= 0x846ca68bu;
    x ^= x >> 16; return x;
}

__device__ __forceinline__ void red4(float* p, float4 v) {
    asm volatile("red.global.add.v4.f32 [%0], {%1,%2,%3,%4};"
                 :: "l"(p), "f"(v.x), "f"(v.y), "f"(v.z), "f"(v.w) : "memory");
}

__device__ __forceinline__ uint32_t smem_u32(const void* p) {
    uint32_t a;
    asm("{ .reg .u64 t; cvta.to.shared.u64 t, %1; cvt.u32.u64 %0, t; }"
        : "=r"(a) : "l"(p));
    return a;
}

// fp16 split: x -> hi(f16x2) + lo(f16x2 of residual); elem .x in low half
__device__ __forceinline__ void cvt_split(float2 x, uint32_t& hi, uint32_t& lo) {
    __half2 h = __float22half2_rn(x);
    float2 hb = __half22float2(h);
    __half2 l = __floats2half2_rn(x.x - hb.x, x.y - hb.y);
    hi = *(uint32_t*)&h;
    lo = *(uint32_t*)&l;
}

__device__ __forceinline__ void mma16816(float* c, const uint32_t* a,
                                         uint32_t b0, uint32_t b1) {
    asm("mma.sync.aligned.m16n8k16.row.col.f32.f16.f16.f32 "
        "{%0,%1,%2,%3}, {%4,%5,%6,%7}, {%8,%9}, {%0,%1,%2,%3};"
        : "+f"(c[0]), "+f"(c[1]), "+f"(c[2]), "+f"(c[3])
        : "r"(a[0]), "r"(a[1]), "r"(a[2]), "r"(a[3]), "r"(b0), "r"(b1));
}

__device__ __forceinline__ void ldm4(uint32_t* r, uint32_t a) {
    asm volatile("ldmatrix.sync.aligned.m8n8.x4.shared.b16 {%0,%1,%2,%3}, [%4];"
                 : "=r"(r[0]), "=r"(r[1]), "=r"(r[2]), "=r"(r[3]) : "r"(a));
}

__device__ __forceinline__ void sts32(uint32_t a, uint32_t v) {
    asm volatile("st.shared.b32 [%0], %1;" :: "r"(a), "r"(v));
}

// ---------------- kernel: hash insert + node aggregation ----------------
__global__ __launch_bounds__(256) void k_insert(const float* __restrict__ ef,
                                                const int* __restrict__ esrc,
                                                const int* __restrict__ edst,
                                                int nn, int E) {
    int i = blockIdx.x * 256 + threadIdx.x;
    if (i >= E) return;
    int s = esrc[i], d = edst[i];
    unsigned int key = (unsigned int)s * (unsigned int)nn + (unsigned int)d;
    unsigned int h = mixh(key) & TMASK;
    for (;;) {
        unsigned int prev = atomicCAS(&g_hkey[h], EMPTYK, key);
        if (prev == EMPTYK) break;
        if (prev == key) { g_dupflag[h] = 1; break; }
        h = (h + 1u) & TMASK;
    }
    g_soe[i] = (int)h;

    const float4* row = (const float4*)(ef + (size_t)i * 64);
    float* ar = g_agg + (size_t)d * 64;
#pragma unroll
    for (int c = 0; c < 16; c++) red4(ar + 4 * c, row[c]);
}

// ---------------- kernel: claim dup ids + accumulate + encode rev-offset ----------------
// g_dupid pre-memset to -1, g_dupsum pre-memset to 0.
__global__ __launch_bounds__(256) void k_dupacc(const float* __restrict__ ef, int E) {
    int i = blockIdx.x * 256 + threadIdx.x;
    if (i >= E) return;
    int slot = g_soe[i];
    int enc = -1;
    if (g_dupflag[slot]) {
        int d = g_dupid[slot];
        if (d < 0) {
            int my = atomicAdd(&g_ndup, 1);
            int old = atomicCAS(&g_dupid[slot], -1, my);
            d = (old == -1) ? my : old;
        }
        if (d < DUPCAP) {
            enc = d * 256;   // byte offset into g_dupsum
            const float4* row = (const float4*)(ef + (size_t)i * 64);
            float* p = g_dupsum + (size_t)d * 64;
#pragma unroll
            for (int c = 0; c < 16; c++) red4(p + 4 * c, row[c]);
        }
    }
    g_soe[i] = enc;
}

// ---------------- fused: smem-staged mirror tiles + ldmatrix HMMA ----------------
// CTA tile = 128 rows: rows 0-63 = edges base..base+63, rows 64-127 = mirrors (+E2).
// A'hi/A'lo: [128 rows][128 f16] each, XOR-swizzled 256B rows. Bf: W frags (R3 k-map,
// N-permuted). Warp grid 4M x 2N: warp = 32 rows x 32 cols. 3-product fp16 split.
__global__ __launch_bounds__(256, 2) void k_fused_mma(const float* __restrict__ ef,
                                                      const int* __restrict__ esrc,
                                                      const float* __restrict__ W,
                                                      const float* __restrict__ bias,
                                                      float* __restrict__ out,
                                                      int E, int ntiles) {
    extern __shared__ __align__(16) char dynsm[];
    const uint32_t smhi = smem_u32(dynsm);          // [0,32K)  A'hi
    const uint32_t smlo = smhi + 32768u;            // [32K,64K) A'lo
    uint4* Bfp = (uint4*)(dynsm + 65536);           // [64K,96K) Bf[8kb][8nb][32lane]

    const int tid = threadIdx.x, lane = tid & 31, wid = tid >> 5;
    const int q = lane & 3, g = lane >> 2;

    // Build W fragments: standard m16n8k16 k-map, N-permuted for float4 stores.
    for (int idx = tid; idx < 2048; idx += 256) {
        int kb = idx >> 8, nb = (idx >> 5) & 7, L = idx & 31;
        int qq = L & 3, nB = L >> 2;
        int n = 16 * (nb >> 1) + ((nB >> 1) << 2) + ((nb & 1) << 1) + (nB & 1);
        int k0 = kb * 16 + 2 * qq;
        uint32_t h0, l0, h1, l1;
        cvt_split(make_float2(W[k0 * 64 + n], W[(k0 + 1) * 64 + n]), h0, l0);
        cvt_split(make_float2(W[(k0 + 8) * 64 + n], W[(k0 + 9) * 64 + n]), h1, l1);
        Bfp[idx] = make_uint4(h0, h1, l0, l1);
    }
    __syncthreads();

    const int E2 = E >> 1;
    const int mg = wid >> 1, nh = wid & 1;
    // ldmatrix per-lane geometry (canonical x4 tiling of a 16x16 block)
    const int lrow = ((lane >> 3) & 1) * 8 + (lane & 7);
    const uint32_t colp = (uint32_t)(lane >> 4) * 16u;
    const int row0 = mg * 32 + lrow;
    const uint32_t sx = (uint32_t)(row0 & 7) << 4;
    const uint32_t rb0 = smhi + (uint32_t)row0 * 256u;
    const uint32_t rb1 = rb0 + 16u * 256u;

    for (int t = blockIdx.x; t < ntiles; t += gridDim.x) {
        const int base = t * 64;

        // ---- staging: warp w stages pairs p = 8w..8w+7 (rows p and p+64) ----
        {
            int p = wid * 8;
#pragma unroll 2
            for (int it = 0; it < 8; it++, p++) {
                int ea = base + p;
                int eac = (ea < E2) ? ea : 0;
                int ebc = eac + E2;
                float2 fa = *(const float2*)(ef + (size_t)eac * 64 + 2 * lane);
                float2 fb = *(const float2*)(ef + (size_t)ebc * 64 + 2 * lane);
                int sa = __ldg(&esrc[eac]), sb = __ldg(&esrc[ebc]);
                int ca = __ldg(&g_soe[ebc]), cb = __ldg(&g_soe[eac]);
                float2 aa = *(const float2*)(g_agg + (size_t)sa * 64 + 2 * lane);
                float2 ab = *(const float2*)(g_agg + (size_t)sb * 64 + 2 * lane);
                float2 ra = fb, rb = fa;   // non-dup: rev = partner's ef (in regs)
                if (ca >= 0)
                    ra = *(const float2*)((const char*)g_dupsum + (uint32_t)ca + 8 * lane);
                if (cb >= 0)
                    rb = *(const float2*)((const char*)g_dupsum + (uint32_t)cb + 8 * lane);
                float2 ma = make_float2(aa.x - ra.x, aa.y - ra.y);
                float2 mb = make_float2(ab.x - rb.x, ab.y - rb.y);

                uint32_t rA = (uint32_t)p * 256u;
                uint32_t rB = rA + 64u * 256u;
                uint32_t swc = (uint32_t)(p & 7) << 4;
                uint32_t c0 = (4u * lane) ^ swc;           // ef -> dcols 2l,2l+1
                uint32_t c1 = (128u + 4u * lane) ^ swc;    // msg -> dcols 64+2l
                uint32_t h, l;
                cvt_split(fa, h, l); sts32(smhi + rA + c0, h); sts32(smlo + rA + c0, l);
                cvt_split(ma, h, l); sts32(smhi + rA + c1, h); sts32(smlo + rA + c1, l);
                cvt_split(fb, h, l); sts32(smhi + rB + c0, h); sts32(smlo + rB + c0, l);
                cvt_split(mb, h, l); sts32(smhi + rB + c1, h); sts32(smlo + rB + c1, l);
            }
        }
        __syncthreads();

        // ---- mainloop: warp tile M=32 (rows mg*32..+31) x N=32 (cols nh*32..+31) ----
        float acc[2][4][4];
#pragma unroll
        for (int mh = 0; mh < 2; mh++)
#pragma unroll
            for (int nb = 0; nb < 4; nb++)
#pragma unroll
                for (int c = 0; c < 4; c++) acc[mh][nb][c] = 0.f;

#pragma unroll
        for (int kb = 0; kb < 8; kb++) {
            uint32_t cofs = (32u * kb + colp) ^ sx;
            uint32_t ah0[4], ah1[4], al0[4], al1[4];
            ldm4(ah0, rb0 + cofs);
            ldm4(ah1, rb1 + cofs);
            ldm4(al0, rb0 + cofs + 32768u);
            ldm4(al1, rb1 + cofs + 32768u);
#pragma unroll
            for (int nb = 0; nb < 4; nb++) {
                uint4 b = Bfp[(kb * 8 + nh * 4 + nb) * 32 + lane];
                mma16816(acc[0][nb], ah0, b.x, b.y);
                mma16816(acc[0][nb], al0, b.x, b.y);
                mma16816(acc[0][nb], ah0, b.z, b.w);
                mma16816(acc[1][nb], ah1, b.x, b.y);
                mma16816(acc[1][nb], al1, b.x, b.y);
                mma16816(acc[1][nb], ah1, b.z, b.w);
            }
        }

        // ---- epilogue: bias + relu + float4 stores (N-permuted) ----
#pragma unroll
        for (int mh = 0; mh < 2; mh++) {
            int r_g = mg * 32 + mh * 16 + g;
            int r_g8 = r_g + 8;
            bool v0 = (base + (r_g & 63)) < E2;
            bool v1 = (base + (r_g8 & 63)) < E2;
            size_t e0 = (r_g < 64) ? (size_t)(base + r_g)
                                   : (size_t)(base + r_g - 64) + (size_t)E2;
            size_t e1 = (r_g8 < 64) ? (size_t)(base + r_g8)
                                    : (size_t)(base + r_g8 - 64) + (size_t)E2;
#pragma unroll
            for (int tt = 0; tt < 2; tt++) {
                int col = nh * 32 + tt * 16 + 4 * q;
                float4 b4 = __ldg((const float4*)(bias + col));
                if (v0) {
                    float4 o;
                    o.x = fmaxf(acc[mh][2 * tt][0] + b4.x, 0.f);
                    o.y = fmaxf(acc[mh][2 * tt][1] + b4.y, 0.f);
                    o.z = fmaxf(acc[mh][2 * tt + 1][0] + b4.z, 0.f);
                    o.w = fmaxf(acc[mh][2 * tt + 1][1] + b4.w, 0.f);
                    *(float4*)(out + e0 * 64 + col) = o;
                }
                if (v1) {
                    float4 o;
                    o.x = fmaxf(acc[mh][2 * tt][2] + b4.x, 0.f);
                    o.y = fmaxf(acc[mh][2 * tt][3] + b4.y, 0.f);
                    o.z = fmaxf(acc[mh][2 * tt + 1][2] + b4.z, 0.f);
                    o.w = fmaxf(acc[mh][2 * tt + 1][3] + b4.w, 0.f);
                    *(float4*)(out + e1 * 64 + col) = o;
                }
            }
        }
        __syncthreads();
    }
}

// ---------------- launch ----------------
extern "C" void kernel_launch(void* const* d_in, const int* in_sizes, int n_in,
                              void* d_out, int out_size) {
    const float* ef   = (const float*)d_in[0];
    const int*   esrc = (const int*)d_in[1];
    const int*   edst = (const int*)d_in[2];
    const float* W    = (const float*)d_in[5];
    const float* bias = (const float*)d_in[6];
    float* out = (float*)d_out;

    int E  = in_sizes[1];
    int nn = in_sizes[3];

    void *p_hkey, *p_flag, *p_agg, *p_dupid, *p_dupsum, *p_ndup;
    cudaGetSymbolAddress(&p_hkey,   g_hkey);
    cudaGetSymbolAddress(&p_flag,   g_dupflag);
    cudaGetSymbolAddress(&p_agg,    g_agg);
    cudaGetSymbolAddress(&p_dupid,  g_dupid);
    cudaGetSymbolAddress(&p_dupsum, g_dupsum);
    cudaGetSymbolAddress(&p_ndup,   g_ndup);

    cudaMemsetAsync(p_hkey,   0xFF, (size_t)TSIZE * 4);
    cudaMemsetAsync(p_flag,   0x00, (size_t)TSIZE);
    cudaMemsetAsync(p_agg,    0x00, (size_t)nn * 64 * 4);
    cudaMemsetAsync(p_dupid,  0xFF, (size_t)TSIZE * 4);
    cudaMemsetAsync(p_dupsum, 0x00, (size_t)DUPCAP * 64 * 4);
    cudaMemsetAsync(p_ndup,   0x00, 4);

    k_insert<<<(E + 255) / 256, 256>>>(ef, esrc, edst, nn, E);
    k_dupacc<<<(E + 255) / 256, 256>>>(ef, E);

    int E2 = E >> 1;
    int ntiles = (E2 + 63) / 64;
    int grid = ntiles < 296 ? ntiles : 296;
    const int SMEMSZ = 98304;
    cudaFuncSetAttribute(k_fused_mma, cudaFuncAttributeMaxDynamicSharedMemorySize, SMEMSZ);
    k_fused_mma<<<grid, 256, SMEMSZ>>>(ef, esrc, W, bias, out, E, ntiles);
}

// round 7
// speedup vs baseline: 1.1598x; 1.1328x over previous
#include <cuda_runtime.h>
#include <cuda_fp16.h>
#include <cstdint>

// ---------------- static scratch ----------------
#define TBITS 21
#define TSIZE (1u << TBITS)
#define TMASK (TSIZE - 1u)
#define EMPTYK 0xFFFFFFFFu
#define MAXE 1050624
#define MAXN 40960
#define DUPCAP 65536

__device__ unsigned int  g_hkey[TSIZE];
__device__ unsigned char g_dupflag[TSIZE];
__device__ int           g_dupid[TSIZE];
__device__ int           g_soe[MAXE];   // pass1: slot of edge; pass2: rev-offset code
__device__ __align__(16) float g_agg[MAXN * 64];
__device__ __align__(16) float g_dupsum[(size_t)DUPCAP * 64];
__device__ int           g_ndup;

// ---------------- helpers ----------------
__device__ __forceinline__ unsigned int mixh(unsigned int x) {
    x ^= x >> 16; x *= 0x7feb352du;
    x ^= x >> 15; x *= 0x846ca68bu;
    x ^= x >> 16; return x;
}

__device__ __forceinline__ void red2(float* p, float2 v) {
    asm volatile("red.global.add.v2.f32 [%0], {%1,%2};"
                 :: "l"(p), "f"(v.x), "f"(v.y) : "memory");
}

__device__ __forceinline__ void red4(float* p, float4 v) {
    asm volatile("red.global.add.v4.f32 [%0], {%1,%2,%3,%4};"
                 :: "l"(p), "f"(v.x), "f"(v.y), "f"(v.z), "f"(v.w) : "memory");
}

__device__ __forceinline__ uint32_t smem_u32(const void* p) {
    uint32_t a;
    asm("{ .reg .u64 t; cvta.to.shared.u64 t, %1; cvt.u32.u64 %0, t; }"
        : "=r"(a) : "l"(p));
    return a;
}

// fp16 split: x -> hi(f16x2) + lo(f16x2 of residual); elem .x in low half
__device__ __forceinline__ void cvt_split(float2 x, uint32_t& hi, uint32_t& lo) {
    __half2 h = __float22half2_rn(x);
    float2 hb = __half22float2(h);
    __half2 l = __floats2half2_rn(x.x - hb.x, x.y - hb.y);
    hi = *(uint32_t*)&h;
    lo = *(uint32_t*)&l;
}

__device__ __forceinline__ void mma16816(float* c, const uint32_t* a,
                                         uint32_t b0, uint32_t b1) {
    asm("mma.sync.aligned.m16n8k16.row.col.f32.f16.f16.f32 "
        "{%0,%1,%2,%3}, {%4,%5,%6,%7}, {%8,%9}, {%0,%1,%2,%3};"
        : "+f"(c[0]), "+f"(c[1]), "+f"(c[2]), "+f"(c[3])
        : "r"(a[0]), "r"(a[1]), "r"(a[2]), "r"(a[3]), "r"(b0), "r"(b1));
}

__device__ __forceinline__ void ldm4(uint32_t* r, uint32_t a) {
    asm volatile("ldmatrix.sync.aligned.m8n8.x4.shared.b16 {%0,%1,%2,%3}, [%4];"
                 : "=r"(r[0]), "=r"(r[1]), "=r"(r[2]), "=r"(r[3]) : "r"(a));
}

__device__ __forceinline__ void sts32(uint32_t a, uint32_t v) {
    asm volatile("st.shared.b32 [%0], %1;" :: "r"(a), "r"(v));
}

// ---------------- kernel: hash insert (thread per edge) ----------------
__global__ __launch_bounds__(256) void k_hash(const int* __restrict__ esrc,
                                              const int* __restrict__ edst,
                                              int nn, int E) {
    int i = blockIdx.x * 256 + threadIdx.x;
    if (i >= E) return;
    int s = esrc[i], d = edst[i];
    unsigned int key = (unsigned int)s * (unsigned int)nn + (unsigned int)d;
    unsigned int h = mixh(key) & TMASK;
    for (;;) {
        unsigned int prev = atomicCAS(&g_hkey[h], EMPTYK, key);
        if (prev == EMPTYK) break;
        if (prev == key) { g_dupflag[h] = 1; break; }
        h = (h + 1u) & TMASK;
    }
    g_soe[i] = (int)h;
}

// ---------------- kernel: coalesced aggregation + dup claim/acc + rev encode ----------
// Warp-per-32-edges: lane j holds edge base+j's dst; warp cooperatively reduces
// each edge's ef row into g_agg[dst] with coalesced red.v2 (2 wavefronts/row).
// Per-thread (rare) dup path claims an id and red4-accumulates into g_dupsum.
__global__ __launch_bounds__(256) void k_aggdup(const float* __restrict__ ef,
                                                const int* __restrict__ edst,
                                                int E) {
    const int lane = threadIdx.x & 31;
    const int wid  = threadIdx.x >> 5;
    const int nw   = gridDim.x * 8;

    for (int base = (blockIdx.x * 8 + wid) * 32; base < E; base += nw * 32) {
        int e = base + lane;
        bool v = e < E;
        int dst = v ? __ldg(&edst[e]) : 0;

        // ---- dup handling (per-thread, scattered but rare) ----
        if (v) {
            int slot = g_soe[e];
            int enc = -1;
            if (g_dupflag[slot]) {
                int d = g_dupid[slot];
                if (d < 0) {
                    int my = atomicAdd(&g_ndup, 1);
                    int old = atomicCAS(&g_dupid[slot], -1, my);
                    d = (old == -1) ? my : old;
                }
                if (d < DUPCAP) {
                    enc = d * 256;
                    const float4* row = (const float4*)(ef + (size_t)e * 64);
                    float* p = g_dupsum + (size_t)d * 64;
#pragma unroll
                    for (int c = 0; c < 16; c++) red4(p + 4 * c, row[c]);
                }
            }
            g_soe[e] = enc;
        }

        // ---- coalesced aggregation ----
        int nvalid = min(32, E - base);
#pragma unroll 4
        for (int j = 0; j < 32; j++) {
            if (j >= nvalid) break;
            int dj = __shfl_sync(0xFFFFFFFFu, dst, j);
            float2 x = *(const float2*)(ef + (size_t)(base + j) * 64 + 2 * lane);
            red2(g_agg + (size_t)dj * 64 + 2 * lane, x);
        }
    }
}

// ---------------- fused: smem-staged mirror tiles + ldmatrix HMMA ----------------
__global__ __launch_bounds__(256, 2) void k_fused_mma(const float* __restrict__ ef,
                                                      const int* __restrict__ esrc,
                                                      const float* __restrict__ W,
                                                      const float* __restrict__ bias,
                                                      float* __restrict__ out,
                                                      int E, int ntiles) {
    extern __shared__ __align__(16) char dynsm[];
    const uint32_t smhi = smem_u32(dynsm);          // [0,32K)  A'hi
    const uint32_t smlo = smhi + 32768u;            // [32K,64K) A'lo
    uint4* Bfp = (uint4*)(dynsm + 65536);           // [64K,96K) Bf[8kb][8nb][32lane]

    const int tid = threadIdx.x, lane = tid & 31, wid = tid >> 5;
    const int q = lane & 3, g = lane >> 2;

    for (int idx = tid; idx < 2048; idx += 256) {
        int kb = idx >> 8, nb = (idx >> 5) & 7, L = idx & 31;
        int qq = L & 3, nB = L >> 2;
        int n = 16 * (nb >> 1) + ((nB >> 1) << 2) + ((nb & 1) << 1) + (nB & 1);
        int k0 = kb * 16 + 2 * qq;
        uint32_t h0, l0, h1, l1;
        cvt_split(make_float2(W[k0 * 64 + n], W[(k0 + 1) * 64 + n]), h0, l0);
        cvt_split(make_float2(W[(k0 + 8) * 64 + n], W[(k0 + 9) * 64 + n]), h1, l1);
        Bfp[idx] = make_uint4(h0, h1, l0, l1);
    }
    __syncthreads();

    const int E2 = E >> 1;
    const int mg = wid >> 1, nh = wid & 1;
    const int lrow = ((lane >> 3) & 1) * 8 + (lane & 7);
    const uint32_t colp = (uint32_t)(lane >> 4) * 16u;
    const int row0 = mg * 32 + lrow;
    const uint32_t sx = (uint32_t)(row0 & 7) << 4;
    const uint32_t rb0 = smhi + (uint32_t)row0 * 256u;
    const uint32_t rb1 = rb0 + 16u * 256u;

    for (int t = blockIdx.x; t < ntiles; t += gridDim.x) {
        const int base = t * 64;

        {
            int p = wid * 8;
#pragma unroll 2
            for (int it = 0; it < 8; it++, p++) {
                int ea = base + p;
                int eac = (ea < E2) ? ea : 0;
                int ebc = eac + E2;
                float2 fa = *(const float2*)(ef + (size_t)eac * 64 + 2 * lane);
                float2 fb = *(const float2*)(ef + (size_t)ebc * 64 + 2 * lane);
                int sa = __ldg(&esrc[eac]), sb = __ldg(&esrc[ebc]);
                int ca = __ldg(&g_soe[ebc]), cb = __ldg(&g_soe[eac]);
                float2 aa = *(const float2*)(g_agg + (size_t)sa * 64 + 2 * lane);
                float2 ab = *(const float2*)(g_agg + (size_t)sb * 64 + 2 * lane);
                float2 ra = fb, rb = fa;
                if (ca >= 0)
                    ra = *(const float2*)((const char*)g_dupsum + (uint32_t)ca + 8 * lane);
                if (cb >= 0)
                    rb = *(const float2*)((const char*)g_dupsum + (uint32_t)cb + 8 * lane);
                float2 ma = make_float2(aa.x - ra.x, aa.y - ra.y);
                float2 mb = make_float2(ab.x - rb.x, ab.y - rb.y);

                uint32_t rA = (uint32_t)p * 256u;
                uint32_t rB = rA + 64u * 256u;
                uint32_t swc = (uint32_t)(p & 7) << 4;
                uint32_t c0 = (4u * lane) ^ swc;
                uint32_t c1 = (128u + 4u * lane) ^ swc;
                uint32_t h, l;
                cvt_split(fa, h, l); sts32(smhi + rA + c0, h); sts32(smlo + rA + c0, l);
                cvt_split(ma, h, l); sts32(smhi + rA + c1, h); sts32(smlo + rA + c1, l);
                cvt_split(fb, h, l); sts32(smhi + rB + c0, h); sts32(smlo + rB + c0, l);
                cvt_split(mb, h, l); sts32(smhi + rB + c1, h); sts32(smlo + rB + c1, l);
            }
        }
        __syncthreads();

        float acc[2][4][4];
#pragma unroll
        for (int mh = 0; mh < 2; mh++)
#pragma unroll
            for (int nb = 0; nb < 4; nb++)
#pragma unroll
                for (int c = 0; c < 4; c++) acc[mh][nb][c] = 0.f;

#pragma unroll
        for (int kb = 0; kb < 8; kb++) {
            uint32_t cofs = (32u * kb + colp) ^ sx;
            uint32_t ah0[4], ah1[4], al0[4], al1[4];
            ldm4(ah0, rb0 + cofs);
            ldm4(ah1, rb1 + cofs);
            ldm4(al0, rb0 + cofs + 32768u);
            ldm4(al1, rb1 + cofs + 32768u);
#pragma unroll
            for (int nb = 0; nb < 4; nb++) {
                uint4 b = Bfp[(kb * 8 + nh * 4 + nb) * 32 + lane];
                mma16816(acc[0][nb], ah0, b.x, b.y);
                mma16816(acc[0][nb], al0, b.x, b.y);
                mma16816(acc[0][nb], ah0, b.z, b.w);
                mma16816(acc[1][nb], ah1, b.x, b.y);
                mma16816(acc[1][nb], al1, b.x, b.y);
                mma16816(acc[1][nb], ah1, b.z, b.w);
            }
        }

#pragma unroll
        for (int mh = 0; mh < 2; mh++) {
            int r_g = mg * 32 + mh * 16 + g;
            int r_g8 = r_g + 8;
            bool v0 = (base + (r_g & 63)) < E2;
            bool v1 = (base + (r_g8 & 63)) < E2;
            size_t e0 = (r_g < 64) ? (size_t)(base + r_g)
                                   : (size_t)(base + r_g - 64) + (size_t)E2;
            size_t e1 = (r_g8 < 64) ? (size_t)(base + r_g8)
                                    : (size_t)(base + r_g8 - 64) + (size_t)E2;
#pragma unroll
            for (int tt = 0; tt < 2; tt++) {
                int col = nh * 32 + tt * 16 + 4 * q;
                float4 b4 = __ldg((const float4*)(bias + col));
                if (v0) {
                    float4 o;
                    o.x = fmaxf(acc[mh][2 * tt][0] + b4.x, 0.f);
                    o.y = fmaxf(acc[mh][2 * tt][1] + b4.y, 0.f);
                    o.z = fmaxf(acc[mh][2 * tt + 1][0] + b4.z, 0.f);
                    o.w = fmaxf(acc[mh][2 * tt + 1][1] + b4.w, 0.f);
                    *(float4*)(out + e0 * 64 + col) = o;
                }
                if (v1) {
                    float4 o;
                    o.x = fmaxf(acc[mh][2 * tt][2] + b4.x, 0.f);
                    o.y = fmaxf(acc[mh][2 * tt][3] + b4.y, 0.f);
                    o.z = fmaxf(acc[mh][2 * tt + 1][2] + b4.z, 0.f);
                    o.w = fmaxf(acc[mh][2 * tt + 1][3] + b4.w, 0.f);
                    *(float4*)(out + e1 * 64 + col) = o;
                }
            }
        }
        __syncthreads();
    }
}

// ---------------- launch ----------------
extern "C" void kernel_launch(void* const* d_in, const int* in_sizes, int n_in,
                              void* d_out, int out_size) {
    const float* ef   = (const float*)d_in[0];
    const int*   esrc = (const int*)d_in[1];
    const int*   edst = (const int*)d_in[2];
    const float* W    = (const float*)d_in[5];
    const float* bias = (const float*)d_in[6];
    float* out = (float*)d_out;

    int E  = in_sizes[1];
    int nn = in_sizes[3];

    void *p_hkey, *p_flag, *p_agg, *p_dupid, *p_dupsum, *p_ndup;
    cudaGetSymbolAddress(&p_hkey,   g_hkey);
    cudaGetSymbolAddress(&p_flag,   g_dupflag);
    cudaGetSymbolAddress(&p_agg,    g_agg);
    cudaGetSymbolAddress(&p_dupid,  g_dupid);
    cudaGetSymbolAddress(&p_dupsum, g_dupsum);
    cudaGetSymbolAddress(&p_ndup,   g_ndup);

    cudaMemsetAsync(p_hkey,   0xFF, (size_t)TSIZE * 4);
    cudaMemsetAsync(p_flag,   0x00, (size_t)TSIZE);
    cudaMemsetAsync(p_agg,    0x00, (size_t)nn * 64 * 4);
    cudaMemsetAsync(p_dupid,  0xFF, (size_t)TSIZE * 4);
    cudaMemsetAsync(p_dupsum, 0x00, (size_t)DUPCAP * 64 * 4);
    cudaMemsetAsync(p_ndup,   0x00, 4);

    k_hash<<<(E + 255) / 256, 256>>>(esrc, edst, nn, E);
    k_aggdup<<<592, 256>>>(ef, edst, E);

    int E2 = E >> 1;
    int ntiles = (E2 + 63) / 64;
    int grid = ntiles < 296 ? ntiles : 296;
    const int SMEMSZ = 98304;
    cudaFuncSetAttribute(k_fused_mma, cudaFuncAttributeMaxDynamicSharedMemorySize, SMEMSZ);
    k_fused_mma<<<grid, 256, SMEMSZ>>>(ef, esrc, W, bias, out, E, ntiles);
}

// round 8
// speedup vs baseline: 1.2716x; 1.0964x over previous
#include <cuda_runtime.h>
#include <cuda_fp16.h>
#include <cstdint>

// ---------------- static scratch ----------------
#define TBITS 21
#define TSIZE (1u << TBITS)
#define TMASK (TSIZE - 1u)
#define EMPTYK 0xFFFFFFFFu
#define MAXE 1050624
#define MAXN 40960
#define DUPCAP 65536

__device__ unsigned int  g_hkey[TSIZE];
__device__ unsigned char g_dupflag[TSIZE];
__device__ int           g_dupid[TSIZE];
__device__ int           g_soe[MAXE];   // pass1: slot of edge; pass2: rev-offset code
__device__ __align__(16) float g_agg[MAXN * 64];
__device__ __align__(16) float g_dupsum[(size_t)DUPCAP * 64];
__device__ int           g_ndup;

// ---------------- helpers ----------------
__device__ __forceinline__ unsigned int mixh(unsigned int x) {
    x ^= x >> 16; x *= 0x7feb352du;
    x ^= x >> 15; x *= 0x846ca68bu;
    x ^= x >> 16; return x;
}

__device__ __forceinline__ void red2(float* p, float2 v) {
    asm volatile("red.global.add.v2.f32 [%0], {%1,%2};"
                 :: "l"(p), "f"(v.x), "f"(v.y) : "memory");
}

__device__ __forceinline__ void red4(float* p, float4 v) {
    asm volatile("red.global.add.v4.f32 [%0], {%1,%2,%3,%4};"
                 :: "l"(p), "f"(v.x), "f"(v.y), "f"(v.z), "f"(v.w) : "memory");
}

// fp16 split: x -> hi(f16x2) + lo(f16x2 of residual); elem .x in low half
__device__ __forceinline__ void cvt_split(float2 x, uint32_t& hi, uint32_t& lo) {
    __half2 h = __float22half2_rn(x);
    float2 hb = __half22float2(h);
    __half2 l = __floats2half2_rn(x.x - hb.x, x.y - hb.y);
    hi = *(uint32_t*)&h;
    lo = *(uint32_t*)&l;
}

__device__ __forceinline__ void mma16816(float* c, const uint32_t* a,
                                         uint32_t b0, uint32_t b1) {
    asm("mma.sync.aligned.m16n8k16.row.col.f32.f16.f16.f32 "
        "{%0,%1,%2,%3}, {%4,%5,%6,%7}, {%8,%9}, {%0,%1,%2,%3};"
        : "+f"(c[0]), "+f"(c[1]), "+f"(c[2]), "+f"(c[3])
        : "r"(a[0]), "r"(a[1]), "r"(a[2]), "r"(a[3]), "r"(b0), "r"(b1));
}

// ---------------- kernel: hash insert (thread per edge) ----------------
__global__ __launch_bounds__(256) void k_hash(const int* __restrict__ esrc,
                                              const int* __restrict__ edst,
                                              int nn, int E) {
    int i = blockIdx.x * 256 + threadIdx.x;
    if (i >= E) return;
    int s = esrc[i], d = edst[i];
    unsigned int key = (unsigned int)s * (unsigned int)nn + (unsigned int)d;
    unsigned int h = mixh(key) & TMASK;
    for (;;) {
        unsigned int prev = atomicCAS(&g_hkey[h], EMPTYK, key);
        if (prev == EMPTYK) break;
        if (prev == key) { g_dupflag[h] = 1; break; }
        h = (h + 1u) & TMASK;
    }
    g_soe[i] = (int)h;
}

// ---------------- kernel: coalesced aggregation + dup claim/acc + rev encode ----------
__global__ __launch_bounds__(256) void k_aggdup(const float* __restrict__ ef,
                                                const int* __restrict__ edst,
                                                int E) {
    const int lane = threadIdx.x & 31;
    const int wid  = threadIdx.x >> 5;
    const int nw   = gridDim.x * 8;

    for (int base = (blockIdx.x * 8 + wid) * 32; base < E; base += nw * 32) {
        int e = base + lane;
        bool v = e < E;
        int dst = v ? __ldg(&edst[e]) : 0;

        // ---- dup handling (per-thread, scattered but rare) ----
        if (v) {
            int slot = g_soe[e];
            int enc = -1;
            if (g_dupflag[slot]) {
                int d = g_dupid[slot];
                if (d < 0) {
                    int my = atomicAdd(&g_ndup, 1);
                    int old = atomicCAS(&g_dupid[slot], -1, my);
                    d = (old == -1) ? my : old;
                }
                if (d < DUPCAP) {
                    enc = d * 256;
                    const float4* row = (const float4*)(ef + (size_t)e * 64);
                    float* p = g_dupsum + (size_t)d * 64;
#pragma unroll
                    for (int c = 0; c < 16; c++) red4(p + 4 * c, row[c]);
                }
            }
            g_soe[e] = enc;
        }

        // ---- coalesced aggregation: warp sweeps its 32 edges ----
        int nvalid = min(32, E - base);
#pragma unroll 4
        for (int j = 0; j < 32; j++) {
            if (j >= nvalid) break;
            int dj = __shfl_sync(0xFFFFFFFFu, dst, j);
            float2 x = *(const float2*)(ef + (size_t)(base + j) * 64 + 2 * lane);
            red2(g_agg + (size_t)dj * 64 + 2 * lane, x);
        }
    }
}

// ---------------- fused: direct-fragment HMMA (R3 structure, flat rev load) ----------
// Per warp: M=32 edges x N=64, K=128 (h = [ef | agg[src]-rev]).
// A fragments generated directly from gmem; W fragments in SMEM.
// 3-product fp16 split: xh*wh + xl*wh + xh*wl.
__global__ __launch_bounds__(256, 2) void k_fused_mma(const float* __restrict__ ef,
                                                      const int* __restrict__ esrc,
                                                      const float* __restrict__ W,
                                                      const float* __restrict__ bias,
                                                      float* __restrict__ out, int E) {
    __shared__ uint2 Bf[2][8][8][32];   // [split][kb][nb][lane] = (b0,b1)  32KB

    const int tid  = threadIdx.x;
    const int lane = tid & 31;
    const int wid  = tid >> 5;
    const int q    = lane & 3;     // k-pair selector within fragment
    const int g    = lane >> 2;    // row-in-group

    // Build W fragments (hi & lo splits) in the exact mma B register layout.
    for (int idx = tid; idx < 4096; idx += 256) {
        int split = idx >> 11, kb = (idx >> 8) & 7, nb = (idx >> 5) & 7, L = idx & 31;
        int qq = L & 3, n = nb * 8 + (L >> 2);
        int k0 = kb * 16 + 2 * qq;
        float w00 = W[k0 * 64 + n],       w01 = W[(k0 + 1) * 64 + n];
        float w10 = W[(k0 + 8) * 64 + n], w11 = W[(k0 + 9) * 64 + n];
        uint32_t h0, l0, h1, l1;
        cvt_split(make_float2(w00, w01), h0, l0);
        cvt_split(make_float2(w10, w11), h1, l1);
        Bf[split][kb][nb][L] = (split == 0) ? make_uint2(h0, h1) : make_uint2(l0, l1);
    }
    __syncthreads();

    const int E2 = E >> 1;
    const int nwt = (E + 31) >> 5;

    for (int wt = blockIdx.x * 8 + wid; wt < nwt; wt += gridDim.x * 8) {
        const int e0 = wt * 32;

        const float2* efp[4];
        const float2* srcp[4];
        const float2* revp[4];
        bool val[4];
#pragma unroll
        for (int j = 0; j < 4; j++) {
            int e = e0 + g + 8 * j;
            val[j] = e < E;
            int ec = val[j] ? e : E - 1;
            efp[j]  = (const float2*)(ef + (size_t)ec * 64);
            srcp[j] = (const float2*)(g_agg + (size_t)__ldg(&esrc[ec]) * 64);
            int mm = (ec < E2) ? (ec + E2) : (ec - E2);
            int enc = __ldg(&g_soe[mm]);    // -1 or byte offset into g_dupsum
            revp[j] = (enc >= 0) ? (const float2*)((const char*)g_dupsum + (uint32_t)enc)
                                 : (const float2*)(ef + (size_t)mm * 64);
        }

        float acc[2][8][4];
#pragma unroll
        for (int mb = 0; mb < 2; mb++)
#pragma unroll
            for (int nb = 0; nb < 8; nb++)
#pragma unroll
                for (int c = 0; c < 4; c++) acc[mb][nb][c] = 0.f;

#pragma unroll
        for (int kb = 0; kb < 8; kb++) {
            uint32_t ah[2][4], al[2][4];
#pragma unroll
            for (int mb = 0; mb < 2; mb++) {
#pragma unroll
                for (int j2 = 0; j2 < 2; j2++) {
                    int j = mb * 2 + j2;
                    float2 x0, x1;
                    if (kb < 4) {
                        x0 = efp[j][kb * 8 + q];
                        x1 = efp[j][kb * 8 + q + 4];
                    } else {
                        int kk = kb - 4;
                        float2 a0 = srcp[j][kk * 8 + q];
                        float2 r0 = revp[j][kk * 8 + q];
                        float2 a1 = srcp[j][kk * 8 + q + 4];
                        float2 r1 = revp[j][kk * 8 + q + 4];
                        x0 = make_float2(a0.x - r0.x, a0.y - r0.y);
                        x1 = make_float2(a1.x - r1.x, a1.y - r1.y);
                    }
                    cvt_split(x0, ah[mb][0 + j2], al[mb][0 + j2]);
                    cvt_split(x1, ah[mb][2 + j2], al[mb][2 + j2]);
                }
            }
#pragma unroll
            for (int nb = 0; nb < 8; nb++) {
                uint2 bh = Bf[0][kb][nb][lane];
                uint2 bl = Bf[1][kb][nb][lane];
#pragma unroll
                for (int mb = 0; mb < 2; mb++) {
                    mma16816(acc[mb][nb], ah[mb], bh.x, bh.y);   // xh*wh
                    mma16816(acc[mb][nb], al[mb], bh.x, bh.y);   // xl*wh
                    mma16816(acc[mb][nb], ah[mb], bl.x, bl.y);   // xh*wl
                }
            }
        }

        // epilogue: bias + relu, coalesced-sector stores
#pragma unroll
        for (int mb = 0; mb < 2; mb++) {
#pragma unroll
            for (int nb = 0; nb < 8; nb++) {
                int col = nb * 8 + 2 * q;
                float2 bv = __ldg((const float2*)(bias + col));
                if (val[mb * 2]) {
                    float2 o = make_float2(fmaxf(acc[mb][nb][0] + bv.x, 0.f),
                                           fmaxf(acc[mb][nb][1] + bv.y, 0.f));
                    *(float2*)(out + (size_t)(e0 + mb * 16 + g) * 64 + col) = o;
                }
                if (val[mb * 2 + 1]) {
                    float2 o = make_float2(fmaxf(acc[mb][nb][2] + bv.x, 0.f),
                                           fmaxf(acc[mb][nb][3] + bv.y, 0.f));
                    *(float2*)(out + (size_t)(e0 + mb * 16 + g + 8) * 64 + col) = o;
                }
            }
        }
    }
}

// ---------------- launch ----------------
extern "C" void kernel_launch(void* const* d_in, const int* in_sizes, int n_in,
                              void* d_out, int out_size) {
    const float* ef   = (const float*)d_in[0];
    const int*   esrc = (const int*)d_in[1];
    const int*   edst = (const int*)d_in[2];
    const float* W    = (const float*)d_in[5];
    const float* bias = (const float*)d_in[6];
    float* out = (float*)d_out;

    int E  = in_sizes[1];
    int nn = in_sizes[3];

    void *p_hkey, *p_flag, *p_agg, *p_dupid, *p_dupsum, *p_ndup;
    cudaGetSymbolAddress(&p_hkey,   g_hkey);
    cudaGetSymbolAddress(&p_flag,   g_dupflag);
    cudaGetSymbolAddress(&p_agg,    g_agg);
    cudaGetSymbolAddress(&p_dupid,  g_dupid);
    cudaGetSymbolAddress(&p_dupsum, g_dupsum);
    cudaGetSymbolAddress(&p_ndup,   g_ndup);

    cudaMemsetAsync(p_hkey,   0xFF, (size_t)TSIZE * 4);
    cudaMemsetAsync(p_flag,   0x00, (size_t)TSIZE);
    cudaMemsetAsync(p_agg,    0x00, (size_t)nn * 64 * 4);
    cudaMemsetAsync(p_dupid,  0xFF, (size_t)TSIZE * 4);
    cudaMemsetAsync(p_dupsum, 0x00, (size_t)DUPCAP * 64 * 4);
    cudaMemsetAsync(p_ndup,   0x00, 4);

    k_hash<<<(E + 255) / 256, 256>>>(esrc, edst, nn, E);
    k_aggdup<<<592, 256>>>(ef, edst, E);

    k_fused_mma<<<296, 256>>>(ef, esrc, W, bias, out, E);
}